// round 1
// baseline (speedup 1.0000x reference)
#include <cuda_runtime.h>
#include <cstdint>

// Problem dims
#define B_    64
#define T_    512
#define V_    512
#define E_    128
#define IMG_  1024
#define H_    512
#define G4    2048   // 4*H

// Recurrent kernel partitioning
#define PODS  4      // batch groups (independent)
#define UBLK  32     // unit-blocks per pod
#define BPB   16     // batches per block
#define UPB   16     // hidden units per block
#define LROWS 64     // gate rows per block (4 gates * UPB)
#define NTHR  256
#define WSTRIDE 516  // padded row stride for W slice in smem (floats)

// Scratch (device globals; no allocation allowed)
__device__ float g_emb_proj[V_ * G4];   // 4 MB
__device__ float g_img_hat[B_ * G4];    // 512 KB
__device__ float g_h[B_ * H_];
__device__ float g_hn[B_ * H_];
__device__ unsigned g_bar_cnt[PODS];
__device__ unsigned g_bar_gen[PODS];

// ---------------------------------------------------------------------------
// Generic small GEMM: C[m][n] = sum_k A[m*lda+k] * Bm[n*ldb+k] (+bias0+bias1)
// All of M, N multiples of 32; K multiple of 32; lda/ldb multiples of 4.
// grid = (N/32, M/32), 256 threads, 2x2 micro-tiles.
// ---------------------------------------------------------------------------
__global__ __launch_bounds__(256)
void gemm_tn(const float* __restrict__ A, int lda,
             const float* __restrict__ Bm, int ldb,
             const float* __restrict__ bias0, const float* __restrict__ bias1,
             float* __restrict__ C, int ldc, int K)
{
    __shared__ float As[32][33];
    __shared__ float Bs[32][33];
    const int tid = threadIdx.x;
    const int m0 = blockIdx.y * 32;
    const int n0 = blockIdx.x * 32;
    const int ty = tid >> 4, tx = tid & 15;
    const int li = tid >> 3;          // 0..31
    const int lk = (tid & 7) * 4;     // 0,4,...,28

    float acc00 = 0.f, acc01 = 0.f, acc10 = 0.f, acc11 = 0.f;

    for (int k0 = 0; k0 < K; k0 += 32) {
        float4 av = *(const float4*)(A  + (size_t)(m0 + li) * lda + k0 + lk);
        float4 bv = *(const float4*)(Bm + (size_t)(n0 + li) * ldb + k0 + lk);
        As[li][lk + 0] = av.x; As[li][lk + 1] = av.y;
        As[li][lk + 2] = av.z; As[li][lk + 3] = av.w;
        Bs[li][lk + 0] = bv.x; Bs[li][lk + 1] = bv.y;
        Bs[li][lk + 2] = bv.z; Bs[li][lk + 3] = bv.w;
        __syncthreads();
        #pragma unroll
        for (int kk = 0; kk < 32; ++kk) {
            float a0 = As[2 * ty][kk],     a1 = As[2 * ty + 1][kk];
            float b0 = Bs[2 * tx][kk],     b1 = Bs[2 * tx + 1][kk];
            acc00 += a0 * b0; acc01 += a0 * b1;
            acc10 += a1 * b0; acc11 += a1 * b1;
        }
        __syncthreads();
    }

    float bj0 = 0.f, bj1 = 0.f;
    if (bias0) { bj0 += bias0[n0 + 2 * tx]; bj1 += bias0[n0 + 2 * tx + 1]; }
    if (bias1) { bj0 += bias1[n0 + 2 * tx]; bj1 += bias1[n0 + 2 * tx + 1]; }

    C[(size_t)(m0 + 2 * ty)     * ldc + n0 + 2 * tx]     = acc00 + bj0;
    C[(size_t)(m0 + 2 * ty)     * ldc + n0 + 2 * tx + 1] = acc01 + bj1;
    C[(size_t)(m0 + 2 * ty + 1) * ldc + n0 + 2 * tx]     = acc10 + bj0;
    C[(size_t)(m0 + 2 * ty + 1) * ldc + n0 + 2 * tx + 1] = acc11 + bj1;
}

// ---------------------------------------------------------------------------
// Persistent LSTM recurrence.
// grid = PODS*UBLK = 128 blocks, 256 threads. Block (pod,ug) owns batches
// [pod*16, pod*16+16) x hidden units [ug*16, ug*16+16) (=> 64 gate rows).
// W_hh slice lives in smem for the whole kernel. Per step: stage h slice from
// L2, 16x64x512 fp32 GEMM (K split 4-way across threads), gate nonlinearity,
// write h slice, pod-local spin barrier (4 independent pods of 32 blocks).
// gx_t comes from the gather: img_hat[b] + emb_proj[x2[b,t]] (precomputed).
// ---------------------------------------------------------------------------
__device__ __forceinline__ float sigmf(float x) {
    return 1.f / (1.f + __expf(-x));
}

__global__ __launch_bounds__(NTHR, 1)
void lstm_kernel(const int* __restrict__ x2, const int* __restrict__ lens,
                 const float* __restrict__ Whh)
{
    extern __shared__ char smraw[];
    float* Wsh   = (float*)smraw;                    // LROWS * WSTRIDE
    float* hsf   = Wsh  + LROWS * WSTRIDE;           // BPB * H_
    float* part  = hsf  + BPB * H_;                  // 4 * BPB * LROWS
    float* imgsh = part + 4 * BPB * LROWS;           // BPB * LROWS
    int*   lensh = (int*)(imgsh + BPB * LROWS);      // BPB
    unsigned* shbase = (unsigned*)(lensh + BPB);     // 1

    const int tid = threadIdx.x;
    const int pod = blockIdx.x / UBLK;
    const int ug  = blockIdx.x % UBLK;
    const int b0  = pod * BPB;
    const int u0  = ug * UPB;

    // Load W_hh slice into smem (rows ordered: r = q*16 + ul -> W_hh[q*H + u0+ul])
    const float4* W4 = (const float4*)Whh;
    for (int idx = tid; idx < LROWS * (H_ / 4); idx += NTHR) {
        int r  = idx >> 7;         // /128
        int k4 = idx & 127;
        int q = r >> 4, ul = r & 15;
        float4 v = W4[(size_t)(q * H_ + u0 + ul) * (H_ / 4) + k4];
        *(float4*)(Wsh + r * WSTRIDE + k4 * 4) = v;
    }
    // img_hat slice (already includes b_ih + b_hh)
    for (int idx = tid; idx < BPB * LROWS; idx += NTHR) {
        int b = idx >> 6, r = idx & 63;
        int q = r >> 4, ul = r & 15;
        imgsh[idx] = g_img_hat[(size_t)(b0 + b) * G4 + q * H_ + u0 + ul];
    }
    if (tid < BPB) lensh[tid] = lens[b0 + tid];
    if (tid == 0) *shbase = g_bar_gen[pod];   // per-replay barrier generation base
    __syncthreads();
    const unsigned genbase = *shbase;

    // gate-phase identity: one (batch, unit) per thread
    const int gb = tid >> 4;   // 0..15
    const int gu = tid & 15;   // 0..15
    // GEMM identity: (K-chunk, batch quad, row lane)
    const int kc = tid >> 6;          // 0..3  -> K chunk of 128
    const int tb = (tid >> 4) & 3;    // 0..3  -> batches 4*tb..4*tb+3
    const int tr = tid & 15;          // 0..15 -> rows {tr, tr+16, tr+32, tr+48}

    float4* hs4 = (float4*)hsf;
    const float4* hrow0 = hs4 + (4 * tb + 0) * 128;
    const float4* hrow1 = hs4 + (4 * tb + 1) * 128;
    const float4* hrow2 = hs4 + (4 * tb + 2) * 128;
    const float4* hrow3 = hs4 + (4 * tb + 3) * 128;
    const float4* wrow0 = (const float4*)(Wsh + (tr     ) * WSTRIDE);
    const float4* wrow1 = (const float4*)(Wsh + (tr + 16) * WSTRIDE);
    const float4* wrow2 = (const float4*)(Wsh + (tr + 32) * WSTRIDE);
    const float4* wrow3 = (const float4*)(Wsh + (tr + 48) * WSTRIDE);
    const int kbase = kc * 32;

    float cstate = 0.f;

    for (int t = 0; t < T_; ++t) {
        // Prefetch the gx gather for this (batch, unit): overlapped with GEMM
        int tok = x2[(size_t)(b0 + gb) * T_ + t];
        const float* ep = g_emb_proj + (size_t)tok * G4 + u0 + gu;
        float e0 = ep[0];
        float e1 = ep[H_];
        float e2 = ep[2 * H_];
        float e3 = ep[3 * H_];

        if (t > 0) {
            // Stage h slice [16][512] from global into smem
            const float4* gh4 = (const float4*)g_h;
            for (int idx = tid; idx < BPB * (H_ / 4); idx += NTHR) {
                hs4[idx] = gh4[(size_t)(b0 + (idx >> 7)) * (H_ / 4) + (idx & 127)];
            }
            __syncthreads();

            float acc[4][4];
            #pragma unroll
            for (int i = 0; i < 4; ++i)
                #pragma unroll
                for (int j = 0; j < 4; ++j) acc[i][j] = 0.f;

            #pragma unroll 4
            for (int k4 = 0; k4 < 32; ++k4) {
                const int kidx = kbase + k4;
                float4 w0 = wrow0[kidx], w1 = wrow1[kidx];
                float4 w2 = wrow2[kidx], w3 = wrow3[kidx];
                float4 h0 = hrow0[kidx], h1 = hrow1[kidx];
                float4 h2 = hrow2[kidx], h3 = hrow3[kidx];
                #define DOT4(hh, ww) (hh.x*ww.x + hh.y*ww.y + hh.z*ww.z + hh.w*ww.w)
                acc[0][0] += DOT4(h0, w0); acc[0][1] += DOT4(h0, w1);
                acc[0][2] += DOT4(h0, w2); acc[0][3] += DOT4(h0, w3);
                acc[1][0] += DOT4(h1, w0); acc[1][1] += DOT4(h1, w1);
                acc[1][2] += DOT4(h1, w2); acc[1][3] += DOT4(h1, w3);
                acc[2][0] += DOT4(h2, w0); acc[2][1] += DOT4(h2, w1);
                acc[2][2] += DOT4(h2, w2); acc[2][3] += DOT4(h2, w3);
                acc[3][0] += DOT4(h3, w0); acc[3][1] += DOT4(h3, w1);
                acc[3][2] += DOT4(h3, w2); acc[3][3] += DOT4(h3, w3);
                #undef DOT4
            }
            // Write K-chunk partials: row = 16*ri + tr, batch = 4*tb + bi
            #pragma unroll
            for (int bi = 0; bi < 4; ++bi)
                #pragma unroll
                for (int ri = 0; ri < 4; ++ri)
                    part[(kc * BPB + 4 * tb + bi) * LROWS + 16 * ri + tr] = acc[bi][ri];
            __syncthreads();
        }

        // Gate phase: thread (gb, gu)
        float gI = e0 + imgsh[gb * LROWS + gu];
        float gF = e1 + imgsh[gb * LROWS + 16 + gu];
        float gG = e2 + imgsh[gb * LROWS + 32 + gu];
        float gO = e3 + imgsh[gb * LROWS + 48 + gu];
        if (t > 0) {
            #pragma unroll
            for (int kk = 0; kk < 4; ++kk) {
                const float* pp = part + (kk * BPB + gb) * LROWS;
                gI += pp[gu];
                gF += pp[16 + gu];
                gG += pp[32 + gu];
                gO += pp[48 + gu];
            }
        }
        float iG = sigmf(gI);
        float fG = sigmf(gF);
        float gT = tanhf(gG);
        float oG = sigmf(gO);
        cstate = fG * cstate + iG * gT;
        float hval = oG * tanhf(cstate);

        g_h[(size_t)(b0 + gb) * H_ + u0 + gu] = hval;
        if (t == lensh[gb] - 1)
            g_hn[(size_t)(b0 + gb) * H_ + u0 + gu] = hval;

        // Pod-local barrier (32 blocks), not needed after the last step.
        if (t < T_ - 1) {
            __threadfence();
            __syncthreads();
            if (tid == 0) {
                unsigned prev = atomicAdd(&g_bar_cnt[pod], 1u);
                if (prev == UBLK - 1) {
                    g_bar_cnt[pod] = 0u;
                    __threadfence();
                    atomicAdd(&g_bar_gen[pod], 1u);
                } else {
                    const unsigned target = genbase + (unsigned)t + 1u;
                    while (*((volatile unsigned*)&g_bar_gen[pod]) < target) { }
                    __threadfence();
                }
            }
            __syncthreads();
        }
    }
}

// ---------------------------------------------------------------------------
// Launch
// ---------------------------------------------------------------------------
static const int LSTM_SMEM =
    (LROWS * WSTRIDE + BPB * H_ + 4 * BPB * LROWS + BPB * LROWS) * 4
    + BPB * 4 + 16;

extern "C" void kernel_launch(void* const* d_in, const int* in_sizes, int n_in,
                              void* d_out, int out_size)
{
    (void)in_sizes; (void)n_in; (void)out_size;
    const float* x1    = (const float*)d_in[0];
    const int*   x2    = (const int*)  d_in[1];
    const int*   lens  = (const int*)  d_in[2];
    const float* emb   = (const float*)d_in[3];
    const float* W_ih  = (const float*)d_in[4];
    const float* W_hh  = (const float*)d_in[5];
    const float* b_ih  = (const float*)d_in[6];
    const float* b_hh  = (const float*)d_in[7];
    const float* W_act = (const float*)d_in[8];
    const float* b_act = (const float*)d_in[9];
    float* out = (float*)d_out;

    float *embp = nullptr, *imgp = nullptr, *hnp = nullptr;
    cudaGetSymbolAddress((void**)&embp, g_emb_proj);
    cudaGetSymbolAddress((void**)&imgp, g_img_hat);
    cudaGetSymbolAddress((void**)&hnp,  g_hn);

    cudaFuncSetAttribute(lstm_kernel,
                         cudaFuncAttributeMaxDynamicSharedMemorySize, LSTM_SMEM);

    // emb_proj[V,4H] = emb @ W_ih[:,IMG:]^T
    gemm_tn<<<dim3(G4 / 32, V_ / 32), 256>>>(
        emb, E_, W_ih + IMG_, E_ + IMG_, nullptr, nullptr, embp, G4, E_);

    // img_hat[B,4H] = x1 @ W_ih[:,:IMG]^T + b_ih + b_hh
    gemm_tn<<<dim3(G4 / 32, B_ / 32), 256>>>(
        x1, IMG_, W_ih, E_ + IMG_, b_ih, b_hh, imgp, G4, IMG_);

    // Recurrence (persistent, 128 co-resident blocks)
    lstm_kernel<<<PODS * UBLK, NTHR, LSTM_SMEM>>>(x2, lens, W_hh);

    // Action head: out[B,A] = hn @ W_act^T + b_act
    gemm_tn<<<dim3(512 / 32, B_ / 32), 256>>>(
        hnp, H_, W_act, H_, b_act, nullptr, out, 512, H_);
}

// round 2
// speedup vs baseline: 1.5729x; 1.5729x over previous
#include <cuda_runtime.h>
#include <cuda_bf16.h>
#include <cstdint>

// Problem dims
#define B_    64
#define T_    512
#define V_    512
#define E_    128
#define IMG_  1024
#define H_    512
#define G4    2048   // 4*H

// Recurrent kernel partitioning
#define PODS  4      // batch groups (independent)
#define UBLK  32     // unit-blocks per pod
#define BPB   16     // batches per block
#define UPB   16     // hidden units per block
#define LROWS 64     // gate rows per block (4 gates * UPB)
#define NTHR  256
#define WPAD  520    // padded row stride (bf16 elems) -> 260 words, +4 banks/row
#define PPAD  68     // padded partials row stride (floats)

// Scratch (device globals; no allocation allowed)
__device__ float g_emb_proj[V_ * G4];   // 4 MB
__device__ float g_img_hat[B_ * G4];    // 512 KB
__device__ __nv_bfloat16 g_hhi[B_ * H_];
__device__ __nv_bfloat16 g_hlo[B_ * H_];
__device__ float g_hn[B_ * H_];
__device__ unsigned g_bar_cnt[PODS];
__device__ unsigned g_bar_gen[PODS];

// ---------------------------------------------------------------------------
// Generic small GEMM: C[m][n] = sum_k A[m*lda+k] * Bm[n*ldb+k] (+bias0+bias1)
// ---------------------------------------------------------------------------
__global__ __launch_bounds__(256)
void gemm_tn(const float* __restrict__ A, int lda,
             const float* __restrict__ Bm, int ldb,
             const float* __restrict__ bias0, const float* __restrict__ bias1,
             float* __restrict__ C, int ldc, int K)
{
    __shared__ float As[32][33];
    __shared__ float Bs[32][33];
    const int tid = threadIdx.x;
    const int m0 = blockIdx.y * 32;
    const int n0 = blockIdx.x * 32;
    const int ty = tid >> 4, tx = tid & 15;
    const int li = tid >> 3;          // 0..31
    const int lk = (tid & 7) * 4;     // 0,4,...,28

    float acc00 = 0.f, acc01 = 0.f, acc10 = 0.f, acc11 = 0.f;

    for (int k0 = 0; k0 < K; k0 += 32) {
        float4 av = *(const float4*)(A  + (size_t)(m0 + li) * lda + k0 + lk);
        float4 bv = *(const float4*)(Bm + (size_t)(n0 + li) * ldb + k0 + lk);
        As[li][lk + 0] = av.x; As[li][lk + 1] = av.y;
        As[li][lk + 2] = av.z; As[li][lk + 3] = av.w;
        Bs[li][lk + 0] = bv.x; Bs[li][lk + 1] = bv.y;
        Bs[li][lk + 2] = bv.z; Bs[li][lk + 3] = bv.w;
        __syncthreads();
        #pragma unroll
        for (int kk = 0; kk < 32; ++kk) {
            float a0 = As[2 * ty][kk],     a1 = As[2 * ty + 1][kk];
            float b0 = Bs[2 * tx][kk],     b1 = Bs[2 * tx + 1][kk];
            acc00 += a0 * b0; acc01 += a0 * b1;
            acc10 += a1 * b0; acc11 += a1 * b1;
        }
        __syncthreads();
    }

    float bj0 = 0.f, bj1 = 0.f;
    if (bias0) { bj0 += bias0[n0 + 2 * tx]; bj1 += bias0[n0 + 2 * tx + 1]; }
    if (bias1) { bj0 += bias1[n0 + 2 * tx]; bj1 += bias1[n0 + 2 * tx + 1]; }

    C[(size_t)(m0 + 2 * ty)     * ldc + n0 + 2 * tx]     = acc00 + bj0;
    C[(size_t)(m0 + 2 * ty)     * ldc + n0 + 2 * tx + 1] = acc01 + bj1;
    C[(size_t)(m0 + 2 * ty + 1) * ldc + n0 + 2 * tx]     = acc10 + bj0;
    C[(size_t)(m0 + 2 * ty + 1) * ldc + n0 + 2 * tx + 1] = acc11 + bj1;
}

// ---------------------------------------------------------------------------
// bf16 warp MMA m16n8k16: D(f32) += A(bf16) * B(bf16)
// ---------------------------------------------------------------------------
__device__ __forceinline__ void mma16816(float& c0, float& c1, float& c2, float& c3,
                                         uint32_t a0, uint32_t a1, uint32_t a2, uint32_t a3,
                                         uint32_t b0, uint32_t b1)
{
    asm volatile(
        "mma.sync.aligned.m16n8k16.row.col.f32.bf16.bf16.f32 "
        "{%0,%1,%2,%3}, {%4,%5,%6,%7}, {%8,%9}, {%0,%1,%2,%3};"
        : "+f"(c0), "+f"(c1), "+f"(c2), "+f"(c3)
        : "r"(a0), "r"(a1), "r"(a2), "r"(a3), "r"(b0), "r"(b1));
}

__device__ __forceinline__ float sigmf(float x) {
    return 1.f / (1.f + __expf(-x));
}

// ---------------------------------------------------------------------------
// Persistent LSTM recurrence — tensor-core version.
// 128 blocks (4 pods x 32), 256 thr. Block owns 16 batches x 64 gate rows,
// K=512. W_hh slice split to bf16 hi/lo resident in smem. h circulates
// through global as bf16 hi/lo (split by producer). Per step:
//   stage h-slice -> smem; 8 warps (4 K-groups x 2 N-groups) each do
//   M16 x N32 x K128 via 3-MMA bf16-split; partials -> smem; gate phase;
//   write h hi/lo; pod-local spin barrier.
// ---------------------------------------------------------------------------
__global__ __launch_bounds__(NTHR, 1)
void lstm_kernel(const int* __restrict__ x2, const int* __restrict__ lens,
                 const float* __restrict__ Whh)
{
    extern __shared__ char smraw[];
    __nv_bfloat16* whi = (__nv_bfloat16*)smraw;           // 64*WPAD
    __nv_bfloat16* wlo = whi + LROWS * WPAD;              // 64*WPAD
    __nv_bfloat16* hhi = wlo + LROWS * WPAD;              // 16*WPAD
    __nv_bfloat16* hlo = hhi + BPB * WPAD;                // 16*WPAD
    float* part  = (float*)(hlo + BPB * WPAD);            // 4*16*PPAD
    float* imgsh = part + 4 * BPB * PPAD;                 // 16*64
    int*   lensh = (int*)(imgsh + BPB * LROWS);           // 16
    unsigned* shbase = (unsigned*)(lensh + BPB);          // 1

    const int tid = threadIdx.x;
    const int pod = blockIdx.x / UBLK;
    const int ug  = blockIdx.x % UBLK;
    const int b0  = pod * BPB;
    const int u0  = ug * UPB;

    // --- W_hh slice: load fp32, split into bf16 hi/lo in smem ---
    // local row r = q*16+ul  <->  W_hh row q*H + u0+ul
    for (int idx = tid; idx < LROWS * H_; idx += NTHR) {
        int r = idx >> 9;          // /512
        int k = idx & 511;
        int q = r >> 4, ul = r & 15;
        float w = Whh[(size_t)(q * H_ + u0 + ul) * H_ + k];
        __nv_bfloat16 hi = __float2bfloat16(w);
        whi[r * WPAD + k] = hi;
        wlo[r * WPAD + k] = __float2bfloat16(w - __bfloat162float(hi));
    }
    // img_hat slice (includes b_ih + b_hh)
    for (int idx = tid; idx < BPB * LROWS; idx += NTHR) {
        int b = idx >> 6, r = idx & 63;
        int q = r >> 4, ul = r & 15;
        imgsh[idx] = g_img_hat[(size_t)(b0 + b) * G4 + q * H_ + u0 + ul];
    }
    if (tid < BPB) lensh[tid] = lens[b0 + tid];
    if (tid == 0) *shbase = g_bar_gen[pod];   // per-replay barrier generation base
    __syncthreads();
    const unsigned genbase = *shbase;

    // gate-phase identity
    const int gb = tid >> 4;   // 0..15 batch
    const int gu = tid & 15;   // 0..15 unit
    // MMA identity
    const int wid = tid >> 5;
    const int kg  = wid >> 1;       // 0..3  K-group of 128
    const int ng  = wid & 1;        // 0..1  N-group of 32 rows
    const int lane = tid & 31;
    const int g  = lane >> 2;       // 0..7
    const int tq = lane & 3;        // 0..3

    const uint32_t* Hh = (const uint32_t*)hhi;   // word stride 260 per row
    const uint32_t* Hl = (const uint32_t*)hlo;
    const uint32_t* Wh = (const uint32_t*)whi;
    const uint32_t* Wl = (const uint32_t*)wlo;

    float cstate = 0.f;

    for (int t = 0; t < T_; ++t) {
        // gx gather for this (batch, unit): issued early, consumed in gate phase
        int tok = x2[(size_t)(b0 + gb) * T_ + t];
        const float* ep = g_emb_proj + (size_t)tok * G4 + u0 + gu;
        float e0 = ep[0];
        float e1 = ep[H_];
        float e2 = ep[2 * H_];
        float e3 = ep[3 * H_];

        if (t > 0) {
            // --- stage h hi/lo slice [16][512] bf16 into smem (vectorized) ---
            const uint4* srchi = (const uint4*)g_hhi;
            const uint4* srclo = (const uint4*)g_hlo;
            #pragma unroll
            for (int i = 0; i < 4; ++i) {
                int idx = tid + i * NTHR;        // 0..1023
                int r = idx >> 6, c = idx & 63;  // row, 16B-chunk
                *(uint4*)((char*)hhi + r * (WPAD * 2) + c * 16) = srchi[(size_t)(b0 + r) * 64 + c];
                *(uint4*)((char*)hlo + r * (WPAD * 2) + c * 16) = srclo[(size_t)(b0 + r) * 64 + c];
            }
            __syncthreads();

            // --- MMA phase: warp does M16 x N32 x K128, 3-MMA bf16 split ---
            float c0[4], c1[4], c2[4], c3[4];
            #pragma unroll
            for (int nt = 0; nt < 4; ++nt) { c0[nt] = c1[nt] = c2[nt] = c3[nt] = 0.f; }

            #pragma unroll
            for (int j = 0; j < 8; ++j) {
                const int kw = kg * 64 + j * 8 + tq;   // word index: (kb + 2t)/2
                uint32_t ah0 = Hh[g * 260 + kw];
                uint32_t ah1 = Hh[(g + 8) * 260 + kw];
                uint32_t ah2 = Hh[g * 260 + kw + 4];
                uint32_t ah3 = Hh[(g + 8) * 260 + kw + 4];
                uint32_t al0 = Hl[g * 260 + kw];
                uint32_t al1 = Hl[(g + 8) * 260 + kw];
                uint32_t al2 = Hl[g * 260 + kw + 4];
                uint32_t al3 = Hl[(g + 8) * 260 + kw + 4];
                #pragma unroll
                for (int nt = 0; nt < 4; ++nt) {
                    const int wr = (ng * 32 + nt * 8 + g) * 260 + kw;
                    uint32_t bh0 = Wh[wr], bh1 = Wh[wr + 4];
                    uint32_t bl0 = Wl[wr], bl1 = Wl[wr + 4];
                    mma16816(c0[nt], c1[nt], c2[nt], c3[nt], ah0, ah1, ah2, ah3, bh0, bh1);
                    mma16816(c0[nt], c1[nt], c2[nt], c3[nt], ah0, ah1, ah2, ah3, bl0, bl1);
                    mma16816(c0[nt], c1[nt], c2[nt], c3[nt], al0, al1, al2, al3, bh0, bh1);
                }
            }
            // --- write K-group partials ---
            float* pb = part + kg * (BPB * PPAD);
            #pragma unroll
            for (int nt = 0; nt < 4; ++nt) {
                int n = ng * 32 + nt * 8 + 2 * tq;
                pb[g * PPAD + n]           = c0[nt];
                pb[g * PPAD + n + 1]       = c1[nt];
                pb[(g + 8) * PPAD + n]     = c2[nt];
                pb[(g + 8) * PPAD + n + 1] = c3[nt];
            }
            __syncthreads();
        }

        // --- gate phase: thread (gb, gu) ---
        float gI = e0 + imgsh[gb * LROWS + gu];
        float gF = e1 + imgsh[gb * LROWS + 16 + gu];
        float gG = e2 + imgsh[gb * LROWS + 32 + gu];
        float gO = e3 + imgsh[gb * LROWS + 48 + gu];
        if (t > 0) {
            #pragma unroll
            for (int kk = 0; kk < 4; ++kk) {
                const float* pp = part + kk * (BPB * PPAD) + gb * PPAD;
                gI += pp[gu];
                gF += pp[16 + gu];
                gG += pp[32 + gu];
                gO += pp[48 + gu];
            }
        }
        float iG = sigmf(gI);
        float fG = sigmf(gF);
        float gT = tanhf(gG);
        float oG = sigmf(gO);
        cstate = fG * cstate + iG * gT;
        float hval = oG * tanhf(cstate);

        __nv_bfloat16 hhv = __float2bfloat16(hval);
        g_hhi[(size_t)(b0 + gb) * H_ + u0 + gu] = hhv;
        g_hlo[(size_t)(b0 + gb) * H_ + u0 + gu] =
            __float2bfloat16(hval - __bfloat162float(hhv));
        if (t == lensh[gb] - 1)
            g_hn[(size_t)(b0 + gb) * H_ + u0 + gu] = hval;

        // --- pod-local barrier (32 blocks) ---
        if (t < T_ - 1) {
            __threadfence();
            __syncthreads();
            if (tid == 0) {
                unsigned prev = atomicAdd(&g_bar_cnt[pod], 1u);
                if (prev == UBLK - 1) {
                    g_bar_cnt[pod] = 0u;
                    __threadfence();
                    atomicAdd(&g_bar_gen[pod], 1u);
                } else {
                    const unsigned target = genbase + (unsigned)t + 1u;
                    while (*((volatile unsigned*)&g_bar_gen[pod]) < target) { }
                    __threadfence();
                }
            }
            __syncthreads();
        }
    }
}

// ---------------------------------------------------------------------------
// Launch
// ---------------------------------------------------------------------------
static const int LSTM_SMEM =
    (LROWS * WPAD * 2 + BPB * WPAD * 2) * 2              // whi/wlo + hhi/hlo (bf16)
    + (4 * BPB * PPAD + BPB * LROWS) * 4                  // part + imgsh
    + BPB * 4 + 16;

extern "C" void kernel_launch(void* const* d_in, const int* in_sizes, int n_in,
                              void* d_out, int out_size)
{
    (void)in_sizes; (void)n_in; (void)out_size;
    const float* x1    = (const float*)d_in[0];
    const int*   x2    = (const int*)  d_in[1];
    const int*   lens  = (const int*)  d_in[2];
    const float* emb   = (const float*)d_in[3];
    const float* W_ih  = (const float*)d_in[4];
    const float* W_hh  = (const float*)d_in[5];
    const float* b_ih  = (const float*)d_in[6];
    const float* b_hh  = (const float*)d_in[7];
    const float* W_act = (const float*)d_in[8];
    const float* b_act = (const float*)d_in[9];
    float* out = (float*)d_out;

    float *embp = nullptr, *imgp = nullptr, *hnp = nullptr;
    cudaGetSymbolAddress((void**)&embp, g_emb_proj);
    cudaGetSymbolAddress((void**)&imgp, g_img_hat);
    cudaGetSymbolAddress((void**)&hnp,  g_hn);

    cudaFuncSetAttribute(lstm_kernel,
                         cudaFuncAttributeMaxDynamicSharedMemorySize, LSTM_SMEM);

    // emb_proj[V,4H] = emb @ W_ih[:,IMG:]^T
    gemm_tn<<<dim3(G4 / 32, V_ / 32), 256>>>(
        emb, E_, W_ih + IMG_, E_ + IMG_, nullptr, nullptr, embp, G4, E_);

    // img_hat[B,4H] = x1 @ W_ih[:,:IMG]^T + b_ih + b_hh
    gemm_tn<<<dim3(G4 / 32, B_ / 32), 256>>>(
        x1, IMG_, W_ih, E_ + IMG_, b_ih, b_hh, imgp, G4, IMG_);

    // Recurrence (persistent, 128 co-resident blocks)
    lstm_kernel<<<PODS * UBLK, NTHR, LSTM_SMEM>>>(x2, lens, W_hh);

    // Action head: out[B,A] = hn @ W_act^T + b_act
    gemm_tn<<<dim3(512 / 32, B_ / 32), 256>>>(
        hnp, H_, W_act, H_, b_act, nullptr, out, 512, H_);
}

// round 3
// speedup vs baseline: 1.7109x; 1.0877x over previous
#include <cuda_runtime.h>
#include <cuda_bf16.h>
#include <cstdint>

// Problem dims
#define B_    64
#define T_    512
#define V_    512
#define E_    128
#define IMG_  1024
#define H_    512
#define G4    2048   // 4*H

// Recurrent kernel partitioning
#define PODS  4      // batch groups (independent)
#define UBLK  32     // unit-blocks per pod
#define BPB   16     // batches per block
#define UPB   16     // hidden units per block
#define LROWS 64     // gate rows per block (4 gates * UPB)
#define NTHR  256
#define WPAD  520    // padded row stride (bf16 elems) -> 260 words, +4 banks/row
#define PPAD  68     // padded partials row stride (floats)

// Scratch (device globals; no allocation allowed)
__device__ float g_emb_proj[V_ * G4];   // 4 MB
__device__ float g_img_hat[B_ * G4];    // 512 KB
__device__ __nv_bfloat16 g_hhi[B_ * H_];
__device__ __nv_bfloat16 g_hlo[B_ * H_];
__device__ float g_hn[B_ * H_];
__device__ unsigned g_bar_cnt[PODS];
__device__ unsigned g_bar_gen[PODS];

// ---------------------------------------------------------------------------
// Generic small GEMM: C[m][n] = sum_k A[m*lda+k] * Bm[n*ldb+k] (+bias0+bias1)
// ---------------------------------------------------------------------------
__global__ __launch_bounds__(256)
void gemm_tn(const float* __restrict__ A, int lda,
             const float* __restrict__ Bm, int ldb,
             const float* __restrict__ bias0, const float* __restrict__ bias1,
             float* __restrict__ C, int ldc, int K)
{
    __shared__ float As[32][33];
    __shared__ float Bs[32][33];
    const int tid = threadIdx.x;
    const int m0 = blockIdx.y * 32;
    const int n0 = blockIdx.x * 32;
    const int ty = tid >> 4, tx = tid & 15;
    const int li = tid >> 3;          // 0..31
    const int lk = (tid & 7) * 4;     // 0,4,...,28

    float acc00 = 0.f, acc01 = 0.f, acc10 = 0.f, acc11 = 0.f;

    for (int k0 = 0; k0 < K; k0 += 32) {
        float4 av = *(const float4*)(A  + (size_t)(m0 + li) * lda + k0 + lk);
        float4 bv = *(const float4*)(Bm + (size_t)(n0 + li) * ldb + k0 + lk);
        As[li][lk + 0] = av.x; As[li][lk + 1] = av.y;
        As[li][lk + 2] = av.z; As[li][lk + 3] = av.w;
        Bs[li][lk + 0] = bv.x; Bs[li][lk + 1] = bv.y;
        Bs[li][lk + 2] = bv.z; Bs[li][lk + 3] = bv.w;
        __syncthreads();
        #pragma unroll
        for (int kk = 0; kk < 32; ++kk) {
            float a0 = As[2 * ty][kk],     a1 = As[2 * ty + 1][kk];
            float b0 = Bs[2 * tx][kk],     b1 = Bs[2 * tx + 1][kk];
            acc00 += a0 * b0; acc01 += a0 * b1;
            acc10 += a1 * b0; acc11 += a1 * b1;
        }
        __syncthreads();
    }

    float bj0 = 0.f, bj1 = 0.f;
    if (bias0) { bj0 += bias0[n0 + 2 * tx]; bj1 += bias0[n0 + 2 * tx + 1]; }
    if (bias1) { bj0 += bias1[n0 + 2 * tx]; bj1 += bias1[n0 + 2 * tx + 1]; }

    C[(size_t)(m0 + 2 * ty)     * ldc + n0 + 2 * tx]     = acc00 + bj0;
    C[(size_t)(m0 + 2 * ty)     * ldc + n0 + 2 * tx + 1] = acc01 + bj1;
    C[(size_t)(m0 + 2 * ty + 1) * ldc + n0 + 2 * tx]     = acc10 + bj0;
    C[(size_t)(m0 + 2 * ty + 1) * ldc + n0 + 2 * tx + 1] = acc11 + bj1;
}

// ---------------------------------------------------------------------------
// bf16 warp MMA m16n8k16: D(f32) += A(bf16) * B(bf16)
// ---------------------------------------------------------------------------
__device__ __forceinline__ void mma16816(float& c0, float& c1, float& c2, float& c3,
                                         uint32_t a0, uint32_t a1, uint32_t a2, uint32_t a3,
                                         uint32_t b0, uint32_t b1)
{
    asm volatile(
        "mma.sync.aligned.m16n8k16.row.col.f32.bf16.bf16.f32 "
        "{%0,%1,%2,%3}, {%4,%5,%6,%7}, {%8,%9}, {%0,%1,%2,%3};"
        : "+f"(c0), "+f"(c1), "+f"(c2), "+f"(c3)
        : "r"(a0), "r"(a1), "r"(a2), "r"(a3), "r"(b0), "r"(b1));
}

__device__ __forceinline__ float sigmf(float x) {
    return 1.f / (1.f + __expf(-x));
}

// ---------------------------------------------------------------------------
// Persistent LSTM recurrence — tensor-core version, W fragments in registers.
// 128 blocks (4 pods x 32), 256 thr. Block owns 16 batches x 64 gate rows,
// K=512. W_hh slice split to bf16 hi/lo, staged via smem once, then held in
// per-thread registers (128 regs) for all 512 steps. Per step:
//   stage h-slice -> smem; 8 warps (4 K-groups x 2 N-groups) each do
//   M16 x N32 x K128 via 3-MMA bf16-split; partials -> smem; gate phase;
//   write h hi/lo; pod-local spin barrier.
// ---------------------------------------------------------------------------
__global__ __launch_bounds__(NTHR, 1)
void lstm_kernel(const int* __restrict__ x2, const int* __restrict__ lens,
                 const float* __restrict__ Whh)
{
    extern __shared__ char smraw[];
    __nv_bfloat16* whi = (__nv_bfloat16*)smraw;           // 64*WPAD (init only)
    __nv_bfloat16* wlo = whi + LROWS * WPAD;              // 64*WPAD (init only)
    __nv_bfloat16* hhi = wlo + LROWS * WPAD;              // 16*WPAD
    __nv_bfloat16* hlo = hhi + BPB * WPAD;                // 16*WPAD
    float* part  = (float*)(hlo + BPB * WPAD);            // 4*16*PPAD
    float* imgsh = part + 4 * BPB * PPAD;                 // 16*64
    int*   lensh = (int*)(imgsh + BPB * LROWS);           // 16
    unsigned* shbase = (unsigned*)(lensh + BPB);          // 1

    const int tid = threadIdx.x;
    const int pod = blockIdx.x / UBLK;
    const int ug  = blockIdx.x % UBLK;
    const int b0  = pod * BPB;
    const int u0  = ug * UPB;

    // --- W_hh slice: load fp32, split into bf16 hi/lo in smem ---
    // local row r = q*16+ul  <->  W_hh row q*H + u0+ul
    for (int idx = tid; idx < LROWS * H_; idx += NTHR) {
        int r = idx >> 9;          // /512
        int k = idx & 511;
        int q = r >> 4, ul = r & 15;
        float w = Whh[(size_t)(q * H_ + u0 + ul) * H_ + k];
        __nv_bfloat16 hi = __float2bfloat16(w);
        whi[r * WPAD + k] = hi;
        wlo[r * WPAD + k] = __float2bfloat16(w - __bfloat162float(hi));
    }
    // img_hat slice (includes b_ih + b_hh)
    for (int idx = tid; idx < BPB * LROWS; idx += NTHR) {
        int b = idx >> 6, r = idx & 63;
        int q = r >> 4, ul = r & 15;
        imgsh[idx] = g_img_hat[(size_t)(b0 + b) * G4 + q * H_ + u0 + ul];
    }
    if (tid < BPB) lensh[tid] = lens[b0 + tid];
    if (tid == 0) *shbase = g_bar_gen[pod];   // per-replay barrier generation base
    __syncthreads();
    const unsigned genbase = *shbase;

    // gate-phase identity
    const int gb = tid >> 4;   // 0..15 batch
    const int gu = tid & 15;   // 0..15 unit
    // MMA identity
    const int wid = tid >> 5;
    const int kg  = wid >> 1;       // 0..3  K-group of 128
    const int ng  = wid & 1;        // 0..1  N-group of 32 rows
    const int lane = tid & 31;
    const int g  = lane >> 2;       // 0..7
    const int tq = lane & 3;        // 0..3

    const uint32_t* Hh = (const uint32_t*)hhi;   // word stride 260 per row
    const uint32_t* Hl = (const uint32_t*)hlo;
    const uint32_t* Wh = (const uint32_t*)whi;
    const uint32_t* Wl = (const uint32_t*)wlo;

    // --- Preload ALL W fragments into registers (held for entire t-loop) ---
    uint32_t bh[64], bl[64];
    #pragma unroll
    for (int j = 0; j < 8; ++j) {
        #pragma unroll
        for (int nt = 0; nt < 4; ++nt) {
            const int wr = (ng * 32 + nt * 8 + g) * 260 + kg * 64 + j * 8 + tq;
            bh[(j * 4 + nt) * 2]     = Wh[wr];
            bh[(j * 4 + nt) * 2 + 1] = Wh[wr + 4];
            bl[(j * 4 + nt) * 2]     = Wl[wr];
            bl[(j * 4 + nt) * 2 + 1] = Wl[wr + 4];
        }
    }

    float cstate = 0.f;

    for (int t = 0; t < T_; ++t) {
        // gx gather for this (batch, unit): issued early, consumed in gate phase
        int tok = x2[(size_t)(b0 + gb) * T_ + t];
        const float* ep = g_emb_proj + (size_t)tok * G4 + u0 + gu;
        float e0 = ep[0];
        float e1 = ep[H_];
        float e2 = ep[2 * H_];
        float e3 = ep[3 * H_];

        if (t > 0) {
            // --- stage h hi/lo slice [16][512] bf16 into smem (vectorized) ---
            const uint4* srchi = (const uint4*)g_hhi;
            const uint4* srclo = (const uint4*)g_hlo;
            #pragma unroll
            for (int i = 0; i < 4; ++i) {
                int idx = tid + i * NTHR;        // 0..1023
                int r = idx >> 6, c = idx & 63;  // row, 16B-chunk
                *(uint4*)((char*)hhi + r * (WPAD * 2) + c * 16) = srchi[(size_t)(b0 + r) * 64 + c];
                *(uint4*)((char*)hlo + r * (WPAD * 2) + c * 16) = srclo[(size_t)(b0 + r) * 64 + c];
            }
            __syncthreads();

            // --- MMA phase: warp does M16 x N32 x K128, 3-MMA bf16 split,
            //     B fragments from registers ---
            float c0[4], c1[4], c2[4], c3[4];
            #pragma unroll
            for (int nt = 0; nt < 4; ++nt) { c0[nt] = c1[nt] = c2[nt] = c3[nt] = 0.f; }

            #pragma unroll
            for (int j = 0; j < 8; ++j) {
                const int kw = kg * 64 + j * 8 + tq;   // word index
                uint32_t ah0 = Hh[g * 260 + kw];
                uint32_t ah1 = Hh[(g + 8) * 260 + kw];
                uint32_t ah2 = Hh[g * 260 + kw + 4];
                uint32_t ah3 = Hh[(g + 8) * 260 + kw + 4];
                uint32_t al0 = Hl[g * 260 + kw];
                uint32_t al1 = Hl[(g + 8) * 260 + kw];
                uint32_t al2 = Hl[g * 260 + kw + 4];
                uint32_t al3 = Hl[(g + 8) * 260 + kw + 4];
                #pragma unroll
                for (int nt = 0; nt < 4; ++nt) {
                    const uint32_t bh0 = bh[(j * 4 + nt) * 2];
                    const uint32_t bh1 = bh[(j * 4 + nt) * 2 + 1];
                    const uint32_t bl0 = bl[(j * 4 + nt) * 2];
                    const uint32_t bl1 = bl[(j * 4 + nt) * 2 + 1];
                    mma16816(c0[nt], c1[nt], c2[nt], c3[nt], ah0, ah1, ah2, ah3, bh0, bh1);
                    mma16816(c0[nt], c1[nt], c2[nt], c3[nt], ah0, ah1, ah2, ah3, bl0, bl1);
                    mma16816(c0[nt], c1[nt], c2[nt], c3[nt], al0, al1, al2, al3, bh0, bh1);
                }
            }
            // --- write K-group partials ---
            float* pb = part + kg * (BPB * PPAD);
            #pragma unroll
            for (int nt = 0; nt < 4; ++nt) {
                int n = ng * 32 + nt * 8 + 2 * tq;
                pb[g * PPAD + n]           = c0[nt];
                pb[g * PPAD + n + 1]       = c1[nt];
                pb[(g + 8) * PPAD + n]     = c2[nt];
                pb[(g + 8) * PPAD + n + 1] = c3[nt];
            }
            __syncthreads();
        }

        // --- gate phase: thread (gb, gu) ---
        float gI = e0 + imgsh[gb * LROWS + gu];
        float gF = e1 + imgsh[gb * LROWS + 16 + gu];
        float gG = e2 + imgsh[gb * LROWS + 32 + gu];
        float gO = e3 + imgsh[gb * LROWS + 48 + gu];
        if (t > 0) {
            #pragma unroll
            for (int kk = 0; kk < 4; ++kk) {
                const float* pp = part + kk * (BPB * PPAD) + gb * PPAD;
                gI += pp[gu];
                gF += pp[16 + gu];
                gG += pp[32 + gu];
                gO += pp[48 + gu];
            }
        }
        float iG = sigmf(gI);
        float fG = sigmf(gF);
        float gT = tanhf(gG);
        float oG = sigmf(gO);
        cstate = fG * cstate + iG * gT;
        float hval = oG * tanhf(cstate);

        __nv_bfloat16 hhv = __float2bfloat16(hval);
        g_hhi[(size_t)(b0 + gb) * H_ + u0 + gu] = hhv;
        g_hlo[(size_t)(b0 + gb) * H_ + u0 + gu] =
            __float2bfloat16(hval - __bfloat162float(hhv));
        if (t == lensh[gb] - 1)
            g_hn[(size_t)(b0 + gb) * H_ + u0 + gu] = hval;

        // --- pod-local barrier (32 blocks) ---
        if (t < T_ - 1) {
            __syncthreads();           // all h stores program-ordered before leader's fence
            if (tid == 0) {
                __threadfence();       // release: make pod's h visible
                unsigned prev = atomicAdd(&g_bar_cnt[pod], 1u);
                if (prev == UBLK - 1) {
                    g_bar_cnt[pod] = 0u;
                    __threadfence();
                    atomicAdd(&g_bar_gen[pod], 1u);
                } else {
                    const unsigned target = genbase + (unsigned)t + 1u;
                    while (*((volatile unsigned*)&g_bar_gen[pod]) < target) { }
                    __threadfence();   // acquire
                }
            }
            __syncthreads();
        }
    }
}

// ---------------------------------------------------------------------------
// Launch
// ---------------------------------------------------------------------------
static const int LSTM_SMEM =
    (LROWS * WPAD * 2 + BPB * WPAD * 2) * 2              // whi/wlo + hhi/hlo (bf16)
    + (4 * BPB * PPAD + BPB * LROWS) * 4                  // part + imgsh
    + BPB * 4 + 16;

extern "C" void kernel_launch(void* const* d_in, const int* in_sizes, int n_in,
                              void* d_out, int out_size)
{
    (void)in_sizes; (void)n_in; (void)out_size;
    const float* x1    = (const float*)d_in[0];
    const int*   x2    = (const int*)  d_in[1];
    const int*   lens  = (const int*)  d_in[2];
    const float* emb   = (const float*)d_in[3];
    const float* W_ih  = (const float*)d_in[4];
    const float* W_hh  = (const float*)d_in[5];
    const float* b_ih  = (const float*)d_in[6];
    const float* b_hh  = (const float*)d_in[7];
    const float* W_act = (const float*)d_in[8];
    const float* b_act = (const float*)d_in[9];
    float* out = (float*)d_out;

    float *embp = nullptr, *imgp = nullptr, *hnp = nullptr;
    cudaGetSymbolAddress((void**)&embp, g_emb_proj);
    cudaGetSymbolAddress((void**)&imgp, g_img_hat);
    cudaGetSymbolAddress((void**)&hnp,  g_hn);

    cudaFuncSetAttribute(lstm_kernel,
                         cudaFuncAttributeMaxDynamicSharedMemorySize, LSTM_SMEM);

    // emb_proj[V,4H] = emb @ W_ih[:,IMG:]^T
    gemm_tn<<<dim3(G4 / 32, V_ / 32), 256>>>(
        emb, E_, W_ih + IMG_, E_ + IMG_, nullptr, nullptr, embp, G4, E_);

    // img_hat[B,4H] = x1 @ W_ih[:,:IMG]^T + b_ih + b_hh
    gemm_tn<<<dim3(G4 / 32, B_ / 32), 256>>>(
        x1, IMG_, W_ih, E_ + IMG_, b_ih, b_hh, imgp, G4, IMG_);

    // Recurrence (persistent, 128 co-resident blocks)
    lstm_kernel<<<PODS * UBLK, NTHR, LSTM_SMEM>>>(x2, lens, W_hh);

    // Action head: out[B,A] = hn @ W_act^T + b_act
    gemm_tn<<<dim3(512 / 32, B_ / 32), 256>>>(
        hnp, H_, W_act, H_, b_act, nullptr, out, 512, H_);
}

// round 4
// speedup vs baseline: 2.5651x; 1.4993x over previous
#include <cuda_runtime.h>
#include <cuda_bf16.h>
#include <cstdint>

// Problem dims
#define B_    64
#define T_    512
#define V_    512
#define E_    128
#define IMG_  1024
#define H_    512
#define G4    2048   // 4*H

// Recurrent kernel partitioning
#define PODS  4      // batch groups (independent)
#define UBLK  32     // unit-blocks per pod
#define BPB   16     // batches per block
#define UPB   16     // hidden units per block
#define LROWS 64     // gate rows per block (4 gates * UPB)
#define NTHR  256
#define WPAD  520    // padded row stride (bf16 elems) -> 260 words, +4 banks/row
#define PPAD  68     // padded partials row stride (floats)

// Scratch (device globals; no allocation allowed)
__device__ float g_emb_proj[V_ * G4];   // 4 MB
__device__ float g_img_hat[B_ * G4];    // 512 KB
__device__ __nv_bfloat16 g_hhi[B_ * H_];
__device__ __nv_bfloat16 g_hlo[B_ * H_];
__device__ float g_hn[B_ * H_];
__device__ unsigned g_cnt[PODS * T_];   // per-step arrival counters (8 KB)

// ---------------------------------------------------------------------------
// Generic small GEMM: C[m][n] = sum_k A[m*lda+k] * Bm[n*ldb+k] (+bias0+bias1)
// ---------------------------------------------------------------------------
__global__ __launch_bounds__(256)
void gemm_tn(const float* __restrict__ A, int lda,
             const float* __restrict__ Bm, int ldb,
             const float* __restrict__ bias0, const float* __restrict__ bias1,
             float* __restrict__ C, int ldc, int K)
{
    __shared__ float As[32][33];
    __shared__ float Bs[32][33];
    const int tid = threadIdx.x;
    const int m0 = blockIdx.y * 32;
    const int n0 = blockIdx.x * 32;
    const int ty = tid >> 4, tx = tid & 15;
    const int li = tid >> 3;          // 0..31
    const int lk = (tid & 7) * 4;     // 0,4,...,28

    float acc00 = 0.f, acc01 = 0.f, acc10 = 0.f, acc11 = 0.f;

    for (int k0 = 0; k0 < K; k0 += 32) {
        float4 av = *(const float4*)(A  + (size_t)(m0 + li) * lda + k0 + lk);
        float4 bv = *(const float4*)(Bm + (size_t)(n0 + li) * ldb + k0 + lk);
        As[li][lk + 0] = av.x; As[li][lk + 1] = av.y;
        As[li][lk + 2] = av.z; As[li][lk + 3] = av.w;
        Bs[li][lk + 0] = bv.x; Bs[li][lk + 1] = bv.y;
        Bs[li][lk + 2] = bv.z; Bs[li][lk + 3] = bv.w;
        __syncthreads();
        #pragma unroll
        for (int kk = 0; kk < 32; ++kk) {
            float a0 = As[2 * ty][kk],     a1 = As[2 * ty + 1][kk];
            float b0 = Bs[2 * tx][kk],     b1 = Bs[2 * tx + 1][kk];
            acc00 += a0 * b0; acc01 += a0 * b1;
            acc10 += a1 * b0; acc11 += a1 * b1;
        }
        __syncthreads();
    }

    float bj0 = 0.f, bj1 = 0.f;
    if (bias0) { bj0 += bias0[n0 + 2 * tx]; bj1 += bias0[n0 + 2 * tx + 1]; }
    if (bias1) { bj0 += bias1[n0 + 2 * tx]; bj1 += bias1[n0 + 2 * tx + 1]; }

    C[(size_t)(m0 + 2 * ty)     * ldc + n0 + 2 * tx]     = acc00 + bj0;
    C[(size_t)(m0 + 2 * ty)     * ldc + n0 + 2 * tx + 1] = acc01 + bj1;
    C[(size_t)(m0 + 2 * ty + 1) * ldc + n0 + 2 * tx]     = acc10 + bj0;
    C[(size_t)(m0 + 2 * ty + 1) * ldc + n0 + 2 * tx + 1] = acc11 + bj1;
}

// Pad / utility kernels (also shift launch index so ncu -s 5 catches lstm_kernel)
__global__ void zero_cnt_kernel() {
    int i = blockIdx.x * blockDim.x + threadIdx.x;
    if (i < PODS * T_) g_cnt[i] = 0u;
}
__global__ void pad_kernel() {}

// ---------------------------------------------------------------------------
// bf16 warp MMA m16n8k16: D(f32) += A(bf16) * B(bf16)
// ---------------------------------------------------------------------------
__device__ __forceinline__ void mma16816(float& c0, float& c1, float& c2, float& c3,
                                         uint32_t a0, uint32_t a1, uint32_t a2, uint32_t a3,
                                         uint32_t b0, uint32_t b1)
{
    asm volatile(
        "mma.sync.aligned.m16n8k16.row.col.f32.bf16.bf16.f32 "
        "{%0,%1,%2,%3}, {%4,%5,%6,%7}, {%8,%9}, {%0,%1,%2,%3};"
        : "+f"(c0), "+f"(c1), "+f"(c2), "+f"(c3)
        : "r"(a0), "r"(a1), "r"(a2), "r"(a3), "r"(b0), "r"(b1));
}

__device__ __forceinline__ float sigmf(float x) {
    return __fdividef(1.f, 1.f + __expf(-x));
}
__device__ __forceinline__ float tanh_fast(float x) {
    float y;
    asm("tanh.approx.f32 %0, %1;" : "=f"(y) : "f"(x));
    return y;
}

// ---------------------------------------------------------------------------
// Persistent LSTM recurrence — tensor cores, W in registers, counter barrier.
// 128 blocks (4 pods x 32), 256 thr. Block owns 16 batches x 64 gate rows,
// K=512. Per step: poll pod counter for step t-1; stage h hi/lo -> smem;
// 8 warps MMA (3-MMA bf16 split, B frags in regs); partials -> smem; gates
// (hw tanh); write h hi/lo; tid0 fence + atomicAdd arrival on cnt[pod][t].
// ---------------------------------------------------------------------------
__global__ __launch_bounds__(NTHR, 1)
void lstm_kernel(const int* __restrict__ x2, const int* __restrict__ lens,
                 const float* __restrict__ Whh)
{
    extern __shared__ char smraw[];
    __nv_bfloat16* whi = (__nv_bfloat16*)smraw;           // 64*WPAD (init; then tokens)
    __nv_bfloat16* wlo = whi + LROWS * WPAD;              // 64*WPAD (init only)
    __nv_bfloat16* hhi = wlo + LROWS * WPAD;              // 16*WPAD
    __nv_bfloat16* hlo = hhi + BPB * WPAD;                // 16*WPAD
    float* part  = (float*)(hlo + BPB * WPAD);            // 4*16*PPAD
    float* imgsh = part + 4 * BPB * PPAD;                 // 16*64
    int*   lensh = (int*)(imgsh + BPB * LROWS);           // 16
    int*   toksh = (int*)whi;                             // aliases whi after init: 16*512 ints

    const int tid = threadIdx.x;
    const int pod = blockIdx.x / UBLK;
    const int ug  = blockIdx.x % UBLK;
    const int b0  = pod * BPB;
    const int u0  = ug * UPB;

    // --- W_hh slice: load fp32, split into bf16 hi/lo in smem ---
    for (int idx = tid; idx < LROWS * H_; idx += NTHR) {
        int r = idx >> 9;          // /512
        int k = idx & 511;
        int q = r >> 4, ul = r & 15;
        float w = Whh[(size_t)(q * H_ + u0 + ul) * H_ + k];
        __nv_bfloat16 hi = __float2bfloat16(w);
        whi[r * WPAD + k] = hi;
        wlo[r * WPAD + k] = __float2bfloat16(w - __bfloat162float(hi));
    }
    // img_hat slice (includes b_ih + b_hh)
    for (int idx = tid; idx < BPB * LROWS; idx += NTHR) {
        int b = idx >> 6, r = idx & 63;
        int q = r >> 4, ul = r & 15;
        imgsh[idx] = g_img_hat[(size_t)(b0 + b) * G4 + q * H_ + u0 + ul];
    }
    if (tid < BPB) lensh[tid] = lens[b0 + tid];
    __syncthreads();

    // identities
    const int gb = tid >> 4;   // 0..15 batch (gate phase)
    const int gu = tid & 15;   // 0..15 unit
    const int wid = tid >> 5;
    const int kg  = wid >> 1;       // 0..3  K-group of 128
    const int ng  = wid & 1;        // 0..1  N-group of 32 rows
    const int lane = tid & 31;
    const int g  = lane >> 2;       // 0..7
    const int tq = lane & 3;        // 0..3

    const uint32_t* Hh = (const uint32_t*)hhi;   // word stride 260 per row
    const uint32_t* Hl = (const uint32_t*)hlo;
    const uint32_t* Wh = (const uint32_t*)whi;
    const uint32_t* Wl = (const uint32_t*)wlo;

    // --- Preload ALL W fragments into registers (held for entire t-loop) ---
    uint32_t bh[64], bl[64];
    #pragma unroll
    for (int j = 0; j < 8; ++j) {
        #pragma unroll
        for (int nt = 0; nt < 4; ++nt) {
            const int wr = (ng * 32 + nt * 8 + g) * 260 + kg * 64 + j * 8 + tq;
            bh[(j * 4 + nt) * 2]     = Wh[wr];
            bh[(j * 4 + nt) * 2 + 1] = Wh[wr + 4];
            bl[(j * 4 + nt) * 2]     = Wl[wr];
            bl[(j * 4 + nt) * 2 + 1] = Wl[wr + 4];
        }
    }
    __syncthreads();   // W smem now dead; reuse whi region for tokens

    // Cache this block's token rows in smem: toksh[b][t]
    for (int idx = tid; idx < BPB * T_; idx += NTHR) {
        int b = idx >> 9, t = idx & 511;
        toksh[idx] = x2[(size_t)(b0 + b) * T_ + t];
    }
    __syncthreads();

    volatile unsigned* cnt = g_cnt + pod * T_;
    float cstate = 0.f;

    for (int t = 0; t < T_; ++t) {
        // gx gather for this (batch, unit): issued early, consumed in gate phase
        int tok = toksh[gb * T_ + t];
        const float* ep = g_emb_proj + (size_t)tok * G4 + u0 + gu;
        float e0 = ep[0];
        float e1 = ep[H_];
        float e2 = ep[2 * H_];
        float e3 = ep[3 * H_];

        if (t > 0) {
            // --- wait for all pod blocks to publish h(t-1) ---
            {
                const unsigned* cp = (const unsigned*)&cnt[t - 1];
                unsigned v;
                do {
                    asm volatile("ld.acquire.gpu.global.u32 %0, [%1];"
                                 : "=r"(v) : "l"(cp));
                } while (v < UBLK);
            }
            // --- stage h hi/lo slice [16][512] bf16 into smem (vectorized) ---
            const uint4* srchi = (const uint4*)g_hhi;
            const uint4* srclo = (const uint4*)g_hlo;
            #pragma unroll
            for (int i = 0; i < 4; ++i) {
                int idx = tid + i * NTHR;        // 0..1023
                int r = idx >> 6, c = idx & 63;  // row, 16B-chunk
                *(uint4*)((char*)hhi + r * (WPAD * 2) + c * 16) = srchi[(size_t)(b0 + r) * 64 + c];
                *(uint4*)((char*)hlo + r * (WPAD * 2) + c * 16) = srclo[(size_t)(b0 + r) * 64 + c];
            }
            __syncthreads();

            // --- MMA phase: warp M16 x N32 x K128, 3-MMA bf16 split ---
            float c0[4], c1[4], c2[4], c3[4];
            #pragma unroll
            for (int nt = 0; nt < 4; ++nt) { c0[nt] = c1[nt] = c2[nt] = c3[nt] = 0.f; }

            #pragma unroll
            for (int j = 0; j < 8; ++j) {
                const int kw = kg * 64 + j * 8 + tq;   // word index
                uint32_t ah0 = Hh[g * 260 + kw];
                uint32_t ah1 = Hh[(g + 8) * 260 + kw];
                uint32_t ah2 = Hh[g * 260 + kw + 4];
                uint32_t ah3 = Hh[(g + 8) * 260 + kw + 4];
                uint32_t al0 = Hl[g * 260 + kw];
                uint32_t al1 = Hl[(g + 8) * 260 + kw];
                uint32_t al2 = Hl[g * 260 + kw + 4];
                uint32_t al3 = Hl[(g + 8) * 260 + kw + 4];
                #pragma unroll
                for (int nt = 0; nt < 4; ++nt) {
                    const uint32_t bh0 = bh[(j * 4 + nt) * 2];
                    const uint32_t bh1 = bh[(j * 4 + nt) * 2 + 1];
                    const uint32_t bl0 = bl[(j * 4 + nt) * 2];
                    const uint32_t bl1 = bl[(j * 4 + nt) * 2 + 1];
                    mma16816(c0[nt], c1[nt], c2[nt], c3[nt], ah0, ah1, ah2, ah3, bh0, bh1);
                    mma16816(c0[nt], c1[nt], c2[nt], c3[nt], ah0, ah1, ah2, ah3, bl0, bl1);
                    mma16816(c0[nt], c1[nt], c2[nt], c3[nt], al0, al1, al2, al3, bh0, bh1);
                }
            }
            // --- write K-group partials ---
            float* pb = part + kg * (BPB * PPAD);
            #pragma unroll
            for (int nt = 0; nt < 4; ++nt) {
                int n = ng * 32 + nt * 8 + 2 * tq;
                pb[g * PPAD + n]           = c0[nt];
                pb[g * PPAD + n + 1]       = c1[nt];
                pb[(g + 8) * PPAD + n]     = c2[nt];
                pb[(g + 8) * PPAD + n + 1] = c3[nt];
            }
            __syncthreads();
        }

        // --- gate phase: thread (gb, gu) ---
        float gI = e0 + imgsh[gb * LROWS + gu];
        float gF = e1 + imgsh[gb * LROWS + 16 + gu];
        float gG = e2 + imgsh[gb * LROWS + 32 + gu];
        float gO = e3 + imgsh[gb * LROWS + 48 + gu];
        if (t > 0) {
            #pragma unroll
            for (int kk = 0; kk < 4; ++kk) {
                const float* pp = part + kk * (BPB * PPAD) + gb * PPAD;
                gI += pp[gu];
                gF += pp[16 + gu];
                gG += pp[32 + gu];
                gO += pp[48 + gu];
            }
        }
        float iG = sigmf(gI);
        float fG = sigmf(gF);
        float gT = tanh_fast(gG);
        float oG = sigmf(gO);
        cstate = fG * cstate + iG * gT;
        float hval = oG * tanh_fast(cstate);

        __nv_bfloat16 hhv = __float2bfloat16(hval);
        g_hhi[(size_t)(b0 + gb) * H_ + u0 + gu] = hhv;
        g_hlo[(size_t)(b0 + gb) * H_ + u0 + gu] =
            __float2bfloat16(hval - __bfloat162float(hhv));
        if (t == lensh[gb] - 1)
            g_hn[(size_t)(b0 + gb) * H_ + u0 + gu] = hval;

        // --- arrive: publish h(t) for the pod ---
        if (t < T_ - 1) {
            __syncthreads();          // all threads' h stores before leader's fence
            if (tid == 0) {
                __threadfence();      // release pod's h to gpu scope
                atomicAdd((unsigned*)&cnt[t], 1u);
            }
        }
    }
}

// ---------------------------------------------------------------------------
// Launch
// ---------------------------------------------------------------------------
static const int LSTM_SMEM =
    (LROWS * WPAD * 2 + BPB * WPAD * 2) * 2              // whi/wlo + hhi/hlo (bf16)
    + (4 * BPB * PPAD + BPB * LROWS) * 4                  // part + imgsh
    + BPB * 4 + 16;

extern "C" void kernel_launch(void* const* d_in, const int* in_sizes, int n_in,
                              void* d_out, int out_size)
{
    (void)in_sizes; (void)n_in; (void)out_size;
    const float* x1    = (const float*)d_in[0];
    const int*   x2    = (const int*)  d_in[1];
    const int*   lens  = (const int*)  d_in[2];
    const float* emb   = (const float*)d_in[3];
    const float* W_ih  = (const float*)d_in[4];
    const float* W_hh  = (const float*)d_in[5];
    const float* b_ih  = (const float*)d_in[6];
    const float* b_hh  = (const float*)d_in[7];
    const float* W_act = (const float*)d_in[8];
    const float* b_act = (const float*)d_in[9];
    float* out = (float*)d_out;

    float *embp = nullptr, *imgp = nullptr, *hnp = nullptr;
    cudaGetSymbolAddress((void**)&embp, g_emb_proj);
    cudaGetSymbolAddress((void**)&imgp, g_img_hat);
    cudaGetSymbolAddress((void**)&hnp,  g_hn);

    cudaFuncSetAttribute(lstm_kernel,
                         cudaFuncAttributeMaxDynamicSharedMemorySize, LSTM_SMEM);

    // #1: emb_proj[V,4H] = emb @ W_ih[:,IMG:]^T
    gemm_tn<<<dim3(G4 / 32, V_ / 32), 256>>>(
        emb, E_, W_ih + IMG_, E_ + IMG_, nullptr, nullptr, embp, G4, E_);

    // #2: img_hat[B,4H] = x1 @ W_ih[:,:IMG]^T + b_ih + b_hh
    gemm_tn<<<dim3(G4 / 32, B_ / 32), 256>>>(
        x1, IMG_, W_ih, E_ + IMG_, b_ih, b_hh, imgp, G4, IMG_);

    // #3..#5: zero barrier counters + pads (also position lstm as 6th launch
    // so the fixed ncu -s 5 -c 1 window profiles it)
    zero_cnt_kernel<<<(PODS * T_ + 255) / 256, 256>>>();
    pad_kernel<<<1, 32>>>();
    pad_kernel<<<1, 32>>>();

    // #6: recurrence (persistent, 128 co-resident blocks)
    lstm_kernel<<<PODS * UBLK, NTHR, LSTM_SMEM>>>(x2, lens, W_hh);

    // #7: action head: out[B,A] = hn @ W_act^T + b_act
    gemm_tn<<<dim3(512 / 32, B_ / 32), 256>>>(
        hnp, H_, W_act, H_, b_act, nullptr, out, 512, H_);
}